// round 14
// baseline (speedup 1.0000x reference)
#include <cuda_runtime.h>
#include <cstdint>

#define NROW   8192
#define DIM    64
#define KTOT   128
#define BM     64
#define BN     128
#define KC     16
#define NTHR   256
#define NCHUNK (KTOT / KC)      // 8
#define TOPK   32
#define PR_ROWS 8               // rows per prep CTA
#define WO_ROWS 4               // rows per writeout CTA

// scratch: U = [nv1|nv2] k-major, V = [nv2|-nv1] k-major
__device__ float Ug[KTOT * NROW];
__device__ float Vg[KTOT * NROW];
__device__ float g_kv[NROW * TOPK];     // top-k values per row
__device__ int   g_kj[NROW * TOPK];     // top-k column indices per row
__device__ int   g_cnt[NROW];           // kept count per row

// XLA EmitFastTanh / Eigen generic_fast_tanh_float, with_fma = true:
// clamp +/-7.99881172180175781, fmaf Horner, final mul separate, IEEE div.
__device__ __forceinline__ float xla_tanh(float x) {
    const float kClamp = 7.99881172180175781f;
    float ax = fabsf(x);
    float xc = fminf(fmaxf(x, -kClamp), kClamp);
    float x2 = __fmul_rn(xc, xc);
    float num = -2.76076847742355e-16f;
    num = fmaf(x2, num, 2.00018790482477e-13f);
    num = fmaf(x2, num, -8.60467152213735e-11f);
    num = fmaf(x2, num, 5.12229709037114e-08f);
    num = fmaf(x2, num, 1.48572235717979e-05f);
    num = fmaf(x2, num, 6.37261928875436e-04f);
    num = fmaf(x2, num, 4.89352455891786e-03f);
    num = __fmul_rn(xc, num);
    float den = 1.19825839466702e-06f;
    den = fmaf(x2, den, 1.18534705686654e-04f);
    den = fmaf(x2, den, 2.26843463243900e-03f);
    den = fmaf(x2, den, 4.89352518554385e-03f);
    float r = __fdiv_rn(num, den);
    return (ax < 0.0004f) ? x : r;
}

// ---------------- kernel A: build U, V (k-major), high-occupancy ------------
__global__ void __launch_bounds__(256) prep_kernel(
    const int* __restrict__ idx,
    const float* __restrict__ emb1, const float* __restrict__ emb2,
    const float* __restrict__ W1, const float* __restrict__ b1,
    const float* __restrict__ W2, const float* __restrict__ b2)
{
    __shared__ float W1s[64][65], W2s[64][65];
    __shared__ float e1s[PR_ROWS][64], e2s[PR_ROWS][64];
    __shared__ float nv1s[64][PR_ROWS + 1], nv2s[64][PR_ROWS + 1];
    __shared__ float b1s[64], b2s[64];
    __shared__ int gix[PR_ROWS];

    int tid = threadIdx.x;
    int r0  = blockIdx.x * PR_ROWS;

    if (tid < PR_ROWS) gix[tid] = idx[r0 + tid];
    if (tid < 64) { b1s[tid] = b1[tid]; b2s[tid] = b2[tid]; }
    for (int i = tid; i < 64 * 64; i += 256) {
        int o = i >> 6, d = i & 63;
        W1s[o][d] = W1[i];
        W2s[o][d] = W2[i];
    }
    __syncthreads();          // gix visible
    for (int i = tid; i < PR_ROWS * 64; i += 256) {
        int rb = i >> 6, d = i & 63;
        int g = gix[rb];
        e1s[rb][d] = emb1[(size_t)g * 64 + d];
        e2s[rb][d] = emb2[(size_t)g * 64 + d];
    }
    __syncthreads();

    int o   = tid & 63;
    int rb0 = tid >> 6;       // 0..3
#pragma unroll
    for (int j = 0; j < PR_ROWS / 4; j++) {
        int rb = rb0 + 4 * j;
        float d1 = 0.f, d2 = 0.f;
#pragma unroll
        for (int d = 0; d < 64; d++) {
            d1 = fmaf(e1s[rb][d], W1s[o][d], d1);
            d2 = fmaf(e2s[rb][d], W2s[o][d], d2);
        }
        nv1s[o][rb] = xla_tanh(__fmul_rn(3.0f, __fadd_rn(d1, b1s[o])));
        nv2s[o][rb] = xla_tanh(__fmul_rn(3.0f, __fadd_rn(d2, b2s[o])));
    }
    __syncthreads();

    // coalesced transposed store-out: 8 consecutive rows per o
    for (int i = tid; i < 64 * PR_ROWS; i += 256) {
        int oo = i >> 3, c = i & 7;
        float n1 = nv1s[oo][c];
        float n2 = nv2s[oo][c];
        size_t base = (size_t)oo * NROW + r0 + c;
        Ug[base]                     = n1;
        Ug[base + (size_t)64 * NROW] = n2;
        Vg[base]                     = n2;
        Vg[base + (size_t)64 * NROW] = -n1;
    }
}

// ---------------- kernel B: stage-1 GEMM (cols 0..127) + ballot top-K
//                             + inline exact fallback for rare rows ----------
#define SM_US 0
#define SM_VS 8192                       // 2 * 16 * 128 = 4096 floats
#define SM_CS (8192 + 4096)              // 64 * 132 = 8448 floats
#define SMEM_FLOATS (SM_CS + 64 * 132)
#define SMEM_BYTES (SMEM_FLOATS * 4)

__global__ void __launch_bounds__(NTHR, 1) stage1_kernel()
{
    extern __shared__ float sm[];
    float* Us  = sm + SM_US;
    float* Vs  = sm + SM_VS;
    float* Cs  = sm + SM_CS;

    __shared__ int   s_unf[64];     // local row ids needing fallback
    __shared__ int   s_nunf;
    __shared__ float s_kv[TOPK];
    __shared__ int   s_kj[TOPK];
    __shared__ float s_thv, s_thaM;
    __shared__ int   s_cnt, s_done;

    int tid = threadIdx.x;
    int r0  = blockIdx.x * BM;
    if (tid == 0) s_nunf = 0;

    // load resident U tile [128][64]
#pragma unroll
    for (int i = 0; i < 8; i++) {
        int f  = tid + NTHR * i;
        int k  = f >> 4;
        int m4 = (f & 15) << 2;
        *(float4*)&Us[k * 64 + m4] = *(const float4*)&Ug[(size_t)k * NROW + r0 + m4];
    }

    int tx  = tid & 31, ty = tid >> 5;
    int rm0 = ty * 4, rm1 = 32 + ty * 4;
    int cn0 = tx * 4;

    // V prefetch: chunk = 16k x 128 cols = 512 float4; 2 per thread
    float4 pf0, pf1;
    int pk0 = tid >> 5,        pn0 = (tid & 31) << 2;
    int pk1 = (tid + 256) >> 5, pn1 = pn0;

    pf0 = *(const float4*)&Vg[(size_t)pk0 * NROW + pn0];
    pf1 = *(const float4*)&Vg[(size_t)pk1 * NROW + pn1];
    *(float4*)&Vs[pk0 * BN + pn0] = pf0;
    *(float4*)&Vs[pk1 * BN + pn1] = pf1;
    __syncthreads();

    float acc[8][4];
#pragma unroll
    for (int i = 0; i < 8; i++)
#pragma unroll
        for (int j = 0; j < 4; j++) acc[i][j] = 0.f;

    int cur = 0;
    for (int kc = 0; kc < NCHUNK; kc++) {
        bool more = (kc + 1 < NCHUNK);
        if (more) {
            size_t base = (size_t)((kc + 1) * KC) * NROW;
            pf0 = *(const float4*)&Vg[base + (size_t)pk0 * NROW + pn0];
            pf1 = *(const float4*)&Vg[base + (size_t)pk1 * NROW + pn1];
        }
        const float* vb = Vs + cur * (KC * BN);
        const float* ub = Us + kc * KC * 64;
#pragma unroll
        for (int k = 0; k < KC; k++) {
            float4 a0 = *(const float4*)&ub[k * 64 + rm0];
            float4 a1 = *(const float4*)&ub[k * 64 + rm1];
            float4 b0 = *(const float4*)&vb[k * BN + cn0];
            float av[8] = {a0.x, a0.y, a0.z, a0.w, a1.x, a1.y, a1.z, a1.w};
            float bv[4] = {b0.x, b0.y, b0.z, b0.w};
#pragma unroll
            for (int i = 0; i < 8; i++)
#pragma unroll
                for (int j = 0; j < 4; j++)
                    acc[i][j] = fmaf(av[i], bv[j], acc[i][j]);
        }
        if (more) {
            float* vw = Vs + (cur ^ 1) * (KC * BN);
            *(float4*)&vw[pk0 * BN + pn0] = pf0;
            *(float4*)&vw[pk1 * BN + pn1] = pf1;
        }
        __syncthreads();
        cur ^= 1;
    }

    // stage C tile to smem [64][132]
#pragma unroll
    for (int i = 0; i < 8; i++) {
        int r = (i < 4) ? (rm0 + i) : (rm1 + i - 4);
        *(float4*)&Cs[r * 132 + cn0] = *(float4*)&acc[i][0];
    }
    __syncthreads();

    // ---- warp-parallel ballot epilogue ----
    // Row is "finished" iff >=32 saturated entries (v == vmax) within these
    // 128 cols; then its top-32 = first 32 such columns (ties at vmax break
    // by lowest index; nothing can rank above vmax).
    const float vmax = xla_tanh(30.0f);
    int lane = tid & 31, warp = tid >> 5;
#pragma unroll
    for (int rr = 0; rr < 8; rr++) {
        int row = warp * 8 + rr;
        const float* crow = &Cs[row * 132];
        unsigned masks[4];
        int pcs[4];
#pragma unroll
        for (int c = 0; c < 4; c++) {
            float a = crow[c * 32 + lane];
            bool pred = false;
            if (a > 2.0f) {  // saturation needs a >= ~2.63; guard is safe
                float v = xla_tanh(__fmul_rn(3.0f, a));
                pred = (v >= vmax);
            }
            masks[c] = __ballot_sync(0xffffffffu, pred);
        }
        int total = 0;
#pragma unroll
        for (int c = 0; c < 4; c++) { pcs[c] = total; total += __popc(masks[c]); }
        int grow = r0 + row;
#pragma unroll
        for (int c = 0; c < 4; c++) {
            if ((masks[c] >> lane) & 1u) {
                int rank = pcs[c] + __popc(masks[c] & ((1u << lane) - 1u));
                if (rank < TOPK) {
                    g_kj[(size_t)grow * TOPK + rank] = c * 32 + lane;
                    g_kv[(size_t)grow * TOPK + rank] = vmax;
                }
            }
        }
        if (lane == 0) {
            if (total >= TOPK) {
                g_cnt[grow] = TOPK;
            } else {
                int slot = atomicAdd(&s_nunf, 1);
                s_unf[slot] = row;
            }
        }
    }
    __syncthreads();

    // ---- inline exact fallback: full-row streaming top-K (rare) ----
    float* as_buf = Cs;   // reuse
    int nunf = s_nunf;
    for (int u = 0; u < nunf; u++) {
        int lrow = s_unf[u];
        int grow = r0 + lrow;
        if (tid == 0) { s_cnt = 0; s_thv = 0.f; s_thaM = 0.f; s_done = 0; }
        __syncthreads();

        for (int jt = 0; jt < NROW / 256; jt++) {
            int j = jt * 256 + tid;
            float dacc = 0.f;
#pragma unroll 16
            for (int k = 0; k < KTOT; k++)
                dacc = fmaf(Us[k * 64 + lrow], Vg[(size_t)k * NROW + j], dacc);
            as_buf[tid] = dacc;
            __syncthreads();

            if (tid == 0) {
                int   cnt  = s_cnt;
                float thv  = s_thv;
                float thaM = s_thaM;
                int jbase = jt * 256;
                for (int c = 0; c < 256; c++) {
                    float a = as_buf[c];
                    if (a <= thaM) continue;
                    float v = xla_tanh(__fmul_rn(3.0f, a));
                    int jidx = jbase + c;
                    if (cnt < TOPK) {
                        s_kv[cnt] = v; s_kj[cnt] = jidx; cnt++;
                        if (cnt == TOPK) {
                            float mv = s_kv[0];
                            for (int s = 1; s < TOPK; s++) mv = fminf(mv, s_kv[s]);
                            thv = mv;
                        }
                    } else if (v > thv) {
                        int ms = 0; float mv = s_kv[0]; int mj = s_kj[0];
                        for (int s = 1; s < TOPK; s++) {
                            if (s_kv[s] < mv || (s_kv[s] == mv && s_kj[s] > mj)) { ms = s; mv = s_kv[s]; mj = s_kj[s]; }
                        }
                        s_kv[ms] = v; s_kj[ms] = jidx;
                        float nm = s_kv[0];
                        for (int s = 1; s < TOPK; s++) nm = fminf(nm, s_kv[s]);
                        thv = nm;
                    } else {
                        thaM = fmaxf(thaM, a);
                    }
                }
                s_cnt = cnt; s_thv = thv; s_thaM = thaM;
                if (cnt == TOPK && thv >= vmax) s_done = 1;
            }
            __syncthreads();
            if (s_done) break;
        }

        if (tid == 0) {
            g_cnt[grow] = s_cnt;
            for (int s = 0; s < s_cnt; s++) {
                g_kv[(size_t)grow * TOPK + s] = s_kv[s];
                g_kj[(size_t)grow * TOPK + s] = s_kj[s];
            }
        }
        __syncthreads();
    }
}

// ---------------- kernel D: writeout — zero rows + embed top-k --------------
__global__ void __launch_bounds__(256) writeout_kernel(float* __restrict__ out)
{
    int r0 = blockIdx.x * WO_ROWS;
    int tid = threadIdx.x;

    // coalesced zero of this block's 4 rows (4 * 8192 floats = 8192 float4)
    float4 z = make_float4(0.f, 0.f, 0.f, 0.f);
    float4* ov = (float4*)(out + (size_t)r0 * NROW);
#pragma unroll
    for (int i = 0; i < WO_ROWS * NROW / 4 / 256; i++)
        ov[tid + 256 * i] = z;

    __syncthreads();   // orders the zero stores before the value stores

    // scatter values: 128 threads = 4 rows x 32 slots
    if (tid < WO_ROWS * TOPK) {
        int row = r0 + (tid >> 5);
        int s   = tid & 31;
        if (s < g_cnt[row]) {
            out[(size_t)row * NROW + g_kj[(size_t)row * TOPK + s]] =
                g_kv[(size_t)row * TOPK + s];
        }
    }
}

extern "C" void kernel_launch(void* const* d_in, const int* in_sizes, int n_in,
                              void* d_out, int out_size)
{
    const int*   idx  = (const int*)d_in[0];
    const float* emb1 = (const float*)d_in[1];
    const float* emb2 = (const float*)d_in[2];
    const float* W1   = (const float*)d_in[3];
    const float* b1   = (const float*)d_in[4];
    const float* W2   = (const float*)d_in[5];
    const float* b2   = (const float*)d_in[6];
    float* out = (float*)d_out;

    static bool configured = false;
    if (!configured) {
        cudaFuncSetAttribute(stage1_kernel, cudaFuncAttributeMaxDynamicSharedMemorySize, SMEM_BYTES);
        configured = true;
    }

    prep_kernel<<<NROW / PR_ROWS, 256>>>(idx, emb1, emb2, W1, b1, W2, b2);
    stage1_kernel<<<NROW / BM, NTHR, SMEM_BYTES>>>();
    writeout_kernel<<<NROW / WO_ROWS, 256>>>(out);
}

// round 15
// speedup vs baseline: 2.2149x; 2.2149x over previous
#include <cuda_runtime.h>
#include <cstdint>

#define NROW   8192
#define DIM    64
#define KTOT   128
#define BM     64
#define BN     256
#define KC     16
#define NTHR   256
#define NCHUNK (KTOT / KC)      // 8
#define TOPK   32
#define FB_ROWS 32              // rows per fallback CTA
#define PR_ROWS 8               // rows per prep CTA
#define WO_ROWS 4               // rows per writeout CTA

// scratch: U = [nv1|nv2] k-major, V = [nv2|-nv1] k-major
__device__ float Ug[KTOT * NROW];
__device__ float Vg[KTOT * NROW];
__device__ int   g_unf[NROW];           // 1 = row needs fallback
__device__ float g_kv[NROW * TOPK];     // top-k values per row
__device__ int   g_kj[NROW * TOPK];     // top-k column indices per row
__device__ int   g_cnt[NROW];           // kept count per row

// XLA EmitFastTanh / Eigen generic_fast_tanh_float, with_fma = true:
// clamp +/-7.99881172180175781, fmaf Horner, final mul separate, IEEE div.
__device__ __forceinline__ float xla_tanh(float x) {
    const float kClamp = 7.99881172180175781f;
    float ax = fabsf(x);
    float xc = fminf(fmaxf(x, -kClamp), kClamp);
    float x2 = __fmul_rn(xc, xc);
    float num = -2.76076847742355e-16f;
    num = fmaf(x2, num, 2.00018790482477e-13f);
    num = fmaf(x2, num, -8.60467152213735e-11f);
    num = fmaf(x2, num, 5.12229709037114e-08f);
    num = fmaf(x2, num, 1.48572235717979e-05f);
    num = fmaf(x2, num, 6.37261928875436e-04f);
    num = fmaf(x2, num, 4.89352455891786e-03f);
    num = __fmul_rn(xc, num);
    float den = 1.19825839466702e-06f;
    den = fmaf(x2, den, 1.18534705686654e-04f);
    den = fmaf(x2, den, 2.26843463243900e-03f);
    den = fmaf(x2, den, 4.89352518554385e-03f);
    float r = __fdiv_rn(num, den);
    return (ax < 0.0004f) ? x : r;
}

// ---------------- kernel A: build U, V (k-major), high-occupancy ------------
// __launch_bounds__(256, 4): cap regs at 64 so 4 CTAs/SM fit (was 165 regs,
// occ 12.4%, 38us). Spills (if any) hit L1 and are noise at this intensity.
__global__ void __launch_bounds__(256, 4) prep_kernel(
    const int* __restrict__ idx,
    const float* __restrict__ emb1, const float* __restrict__ emb2,
    const float* __restrict__ W1, const float* __restrict__ b1,
    const float* __restrict__ W2, const float* __restrict__ b2)
{
    __shared__ float W1s[64][65], W2s[64][65];
    __shared__ float e1s[PR_ROWS][64], e2s[PR_ROWS][64];
    __shared__ float nv1s[64][PR_ROWS + 1], nv2s[64][PR_ROWS + 1];
    __shared__ float b1s[64], b2s[64];
    __shared__ int gix[PR_ROWS];

    int tid = threadIdx.x;
    int r0  = blockIdx.x * PR_ROWS;

    if (tid < PR_ROWS) gix[tid] = idx[r0 + tid];
    if (tid < 64) { b1s[tid] = b1[tid]; b2s[tid] = b2[tid]; }
    for (int i = tid; i < 64 * 64; i += 256) {
        int o = i >> 6, d = i & 63;
        W1s[o][d] = W1[i];
        W2s[o][d] = W2[i];
    }
    __syncthreads();          // gix visible
    for (int i = tid; i < PR_ROWS * 64; i += 256) {
        int rb = i >> 6, d = i & 63;
        int g = gix[rb];
        e1s[rb][d] = emb1[(size_t)g * 64 + d];
        e2s[rb][d] = emb2[(size_t)g * 64 + d];
    }
    __syncthreads();

    int o   = tid & 63;
    int rb0 = tid >> 6;       // 0..3
#pragma unroll
    for (int j = 0; j < PR_ROWS / 4; j++) {
        int rb = rb0 + 4 * j;
        float d1 = 0.f, d2 = 0.f;
#pragma unroll
        for (int d = 0; d < 64; d++) {
            d1 = fmaf(e1s[rb][d], W1s[o][d], d1);
            d2 = fmaf(e2s[rb][d], W2s[o][d], d2);
        }
        nv1s[o][rb] = xla_tanh(__fmul_rn(3.0f, __fadd_rn(d1, b1s[o])));
        nv2s[o][rb] = xla_tanh(__fmul_rn(3.0f, __fadd_rn(d2, b2s[o])));
    }
    __syncthreads();

    // coalesced transposed store-out: 8 consecutive rows per o
    for (int i = tid; i < 64 * PR_ROWS; i += 256) {
        int oo = i >> 3, c = i & 7;
        float n1 = nv1s[oo][c];
        float n2 = nv2s[oo][c];
        size_t base = (size_t)oo * NROW + r0 + c;
        Ug[base]                     = n1;
        Ug[base + (size_t)64 * NROW] = n2;
        Vg[base]                     = n2;
        Vg[base + (size_t)64 * NROW] = -n1;
    }
}

// ---------------- kernel B: stage-1 GEMM (cols 0..255) + ballot top-K -------
#define SM_US 0
#define SM_VS 8192
#define SM_CS 16384
#define SMEM_FLOATS (SM_CS + 64 * 260)
#define SMEM_BYTES (SMEM_FLOATS * 4)

__global__ void __launch_bounds__(NTHR, 1) stage1_kernel()
{
    extern __shared__ float sm[];
    float* Us  = sm + SM_US;
    float* Vs  = sm + SM_VS;
    float* Cs  = sm + SM_CS;

    int tid = threadIdx.x;
    int r0  = blockIdx.x * BM;

    // load resident U tile [128][64]
#pragma unroll
    for (int i = 0; i < 8; i++) {
        int f  = tid + NTHR * i;
        int k  = f >> 4;
        int m4 = (f & 15) << 2;
        *(float4*)&Us[k * 64 + m4] = *(const float4*)&Ug[(size_t)k * NROW + r0 + m4];
    }

    int tx  = tid & 31, ty = tid >> 5;
    int rm0 = ty * 4, rm1 = 32 + ty * 4;
    int cn0 = tx * 4, cn1 = 128 + tx * 4;

    float4 pf0, pf1, pf2, pf3;
    int pk0, pn0, pk1, pn1, pk2, pn2, pk3, pn3;

    {
        int f;
        f = tid;             pk0 = f >> 6; pn0 = (f & 63) << 2;
        f = tid + NTHR;      pk1 = f >> 6; pn1 = (f & 63) << 2;
        f = tid + 2 * NTHR;  pk2 = f >> 6; pn2 = (f & 63) << 2;
        f = tid + 3 * NTHR;  pk3 = f >> 6; pn3 = (f & 63) << 2;
        pf0 = *(const float4*)&Vg[(size_t)pk0 * NROW + pn0];
        pf1 = *(const float4*)&Vg[(size_t)pk1 * NROW + pn1];
        pf2 = *(const float4*)&Vg[(size_t)pk2 * NROW + pn2];
        pf3 = *(const float4*)&Vg[(size_t)pk3 * NROW + pn3];
        *(float4*)&Vs[pk0 * BN + pn0] = pf0;
        *(float4*)&Vs[pk1 * BN + pn1] = pf1;
        *(float4*)&Vs[pk2 * BN + pn2] = pf2;
        *(float4*)&Vs[pk3 * BN + pn3] = pf3;
    }
    __syncthreads();

    float acc[8][8];
#pragma unroll
    for (int i = 0; i < 8; i++)
#pragma unroll
        for (int j = 0; j < 8; j++) acc[i][j] = 0.f;

    int cur = 0;
    for (int kc = 0; kc < NCHUNK; kc++) {
        bool more = (kc + 1 < NCHUNK);
        if (more) {
            size_t base = (size_t)((kc + 1) * KC) * NROW;
            pf0 = *(const float4*)&Vg[base + (size_t)pk0 * NROW + pn0];
            pf1 = *(const float4*)&Vg[base + (size_t)pk1 * NROW + pn1];
            pf2 = *(const float4*)&Vg[base + (size_t)pk2 * NROW + pn2];
            pf3 = *(const float4*)&Vg[base + (size_t)pk3 * NROW + pn3];
        }
        const float* vb = Vs + cur * (KC * BN);
        const float* ub = Us + kc * KC * 64;
#pragma unroll
        for (int k = 0; k < KC; k++) {
            float4 a0 = *(const float4*)&ub[k * 64 + rm0];
            float4 a1 = *(const float4*)&ub[k * 64 + rm1];
            float4 b0 = *(const float4*)&vb[k * BN + cn0];
            float4 b1 = *(const float4*)&vb[k * BN + cn1];
            float av[8] = {a0.x, a0.y, a0.z, a0.w, a1.x, a1.y, a1.z, a1.w};
            float bv[8] = {b0.x, b0.y, b0.z, b0.w, b1.x, b1.y, b1.z, b1.w};
#pragma unroll
            for (int i = 0; i < 8; i++)
#pragma unroll
                for (int j = 0; j < 8; j++)
                    acc[i][j] = fmaf(av[i], bv[j], acc[i][j]);
        }
        if (more) {
            float* vw = Vs + (cur ^ 1) * (KC * BN);
            *(float4*)&vw[pk0 * BN + pn0] = pf0;
            *(float4*)&vw[pk1 * BN + pn1] = pf1;
            *(float4*)&vw[pk2 * BN + pn2] = pf2;
            *(float4*)&vw[pk3 * BN + pn3] = pf3;
        }
        __syncthreads();
        cur ^= 1;
    }

    // stage C tile to smem
#pragma unroll
    for (int i = 0; i < 8; i++) {
        int r = (i < 4) ? (rm0 + i) : (rm1 + i - 4);
        *(float4*)&Cs[r * 260 + cn0] = *(float4*)&acc[i][0];
        *(float4*)&Cs[r * 260 + cn1] = *(float4*)&acc[i][4];
    }
    __syncthreads();

    // ---- warp-parallel ballot epilogue ----
    // Row is "finished" iff >=32 saturated entries (v == vmax) within these
    // 256 cols; then its top-32 = first 32 such columns (ties at vmax break
    // by lowest index; nothing can rank above vmax). Non-finished rows go to
    // the general fallback.
    const float vmax = xla_tanh(30.0f);
    int lane = tid & 31, warp = tid >> 5;
#pragma unroll
    for (int rr = 0; rr < 8; rr++) {
        int row = warp * 8 + rr;
        const float* crow = &Cs[row * 260];
        unsigned masks[8];
        int pcs[8];
#pragma unroll
        for (int c = 0; c < 8; c++) {
            float a = crow[c * 32 + lane];
            bool pred = false;
            if (a > 2.0f) {  // saturation needs a >= ~2.63; guard is safe
                float v = xla_tanh(__fmul_rn(3.0f, a));
                pred = (v >= vmax);
            }
            masks[c] = __ballot_sync(0xffffffffu, pred);
        }
        int total = 0;
#pragma unroll
        for (int c = 0; c < 8; c++) { pcs[c] = total; total += __popc(masks[c]); }
        int grow = r0 + row;
#pragma unroll
        for (int c = 0; c < 8; c++) {
            if ((masks[c] >> lane) & 1u) {
                int rank = pcs[c] + __popc(masks[c] & ((1u << lane) - 1u));
                if (rank < TOPK) {
                    g_kj[(size_t)grow * TOPK + rank] = c * 32 + lane;
                    g_kv[(size_t)grow * TOPK + rank] = vmax;
                }
            }
        }
        if (lane == 0) {
            bool fin = (total >= TOPK);
            g_unf[grow] = fin ? 0 : 1;
            g_cnt[grow] = fin ? TOPK : 0;   // fallback overwrites if unfinished
        }
    }
}

// ---------------- kernel C: fallback — full-row top-K for unfinished rows ---
__global__ void __launch_bounds__(256) fallback_kernel()
{
    __shared__ float us[KTOT];
    __shared__ float as[256];
    __shared__ float kv[TOPK];
    __shared__ int   kj[TOPK];
    __shared__ float s_thv, s_thaM;
    __shared__ int   s_cnt, s_done;
    __shared__ int   flags[FB_ROWS];

    int tid = threadIdx.x;
    const float vmax = xla_tanh(30.0f);

    // parallel flag preload (serial dependent g_unf loads cost ~10us before)
    if (tid < FB_ROWS) flags[tid] = g_unf[blockIdx.x * FB_ROWS + tid];
    __syncthreads();

    for (int rr = 0; rr < FB_ROWS; rr++) {
        if (flags[rr] == 0) continue;      // uniform across block (smem read)
        int row = blockIdx.x * FB_ROWS + rr;

        if (tid < KTOT) us[tid] = Ug[(size_t)tid * NROW + row];
        if (tid == 0) { s_cnt = 0; s_thv = 0.f; s_thaM = 0.f; s_done = 0; }
        __syncthreads();

        for (int jt = 0; jt < NROW / 256; jt++) {
            int j = jt * 256 + tid;
            float acc = 0.f;
#pragma unroll 16
            for (int k = 0; k < KTOT; k++)
                acc = fmaf(us[k], Vg[(size_t)k * NROW + j], acc);
            as[tid] = acc;
            __syncthreads();

            if (tid == 0) {
                int   cnt  = s_cnt;
                float thv  = s_thv;
                float thaM = s_thaM;
                int jbase = jt * 256;
                for (int c = 0; c < 256; c++) {
                    float a = as[c];
                    if (a <= thaM) continue;
                    float v = xla_tanh(__fmul_rn(3.0f, a));
                    int jidx = jbase + c;
                    if (cnt < TOPK) {
                        kv[cnt] = v; kj[cnt] = jidx; cnt++;
                        if (cnt == TOPK) {
                            float mv = kv[0];
                            for (int s = 1; s < TOPK; s++) mv = fminf(mv, kv[s]);
                            thv = mv;
                        }
                    } else if (v > thv) {
                        int ms = 0; float mv = kv[0]; int mj = kj[0];
                        for (int s = 1; s < TOPK; s++) {
                            if (kv[s] < mv || (kv[s] == mv && kj[s] > mj)) { ms = s; mv = kv[s]; mj = kj[s]; }
                        }
                        kv[ms] = v; kj[ms] = jidx;
                        float nm = kv[0];
                        for (int s = 1; s < TOPK; s++) nm = fminf(nm, kv[s]);
                        thv = nm;
                    } else {
                        thaM = fmaxf(thaM, a);
                    }
                }
                s_cnt = cnt; s_thv = thv; s_thaM = thaM;
                if (cnt == TOPK && thv >= vmax) s_done = 1;
            }
            __syncthreads();
            if (s_done) break;
        }

        if (tid == 0) {
            g_cnt[row] = s_cnt;
            for (int s = 0; s < s_cnt; s++) {
                g_kv[(size_t)row * TOPK + s] = kv[s];
                g_kj[(size_t)row * TOPK + s] = kj[s];
            }
        }
        __syncthreads();
    }
}

// ---------------- kernel D: writeout — zero rows + embed top-k --------------
__global__ void __launch_bounds__(256) writeout_kernel(float* __restrict__ out)
{
    int r0 = blockIdx.x * WO_ROWS;
    int tid = threadIdx.x;

    // coalesced zero of this block's 4 rows (4 * 8192 floats = 8192 float4)
    float4 z = make_float4(0.f, 0.f, 0.f, 0.f);
    float4* ov = (float4*)(out + (size_t)r0 * NROW);
#pragma unroll
    for (int i = 0; i < WO_ROWS * NROW / 4 / 256; i++)
        ov[tid + 256 * i] = z;

    __syncthreads();   // orders the zero stores before the value stores

    // scatter values: 128 threads = 4 rows x 32 slots
    if (tid < WO_ROWS * TOPK) {
        int row = r0 + (tid >> 5);
        int s   = tid & 31;
        if (s < g_cnt[row]) {
            out[(size_t)row * NROW + g_kj[(size_t)row * TOPK + s]] =
                g_kv[(size_t)row * TOPK + s];
        }
    }
}

extern "C" void kernel_launch(void* const* d_in, const int* in_sizes, int n_in,
                              void* d_out, int out_size)
{
    const int*   idx  = (const int*)d_in[0];
    const float* emb1 = (const float*)d_in[1];
    const float* emb2 = (const float*)d_in[2];
    const float* W1   = (const float*)d_in[3];
    const float* b1   = (const float*)d_in[4];
    const float* W2   = (const float*)d_in[5];
    const float* b2   = (const float*)d_in[6];
    float* out = (float*)d_out;

    static bool configured = false;
    if (!configured) {
        cudaFuncSetAttribute(stage1_kernel, cudaFuncAttributeMaxDynamicSharedMemorySize, SMEM_BYTES);
        configured = true;
    }

    prep_kernel<<<NROW / PR_ROWS, 256>>>(idx, emb1, emb2, W1, b1, W2, b2);
    stage1_kernel<<<NROW / BM, NTHR, SMEM_BYTES>>>();
    fallback_kernel<<<NROW / FB_ROWS, 256>>>();
    writeout_kernel<<<NROW / WO_ROWS, 256>>>(out);
}

// round 17
// speedup vs baseline: 2.7150x; 1.2258x over previous
#include <cuda_runtime.h>
#include <cstdint>

#define NROW   8192
#define DIM    64
#define KTOT   128
#define BM     64
#define BN     256
#define KC     16
#define NTHR   256
#define NCHUNK (KTOT / KC)      // 8
#define TOPK   32
#define PR_ROWS 32              // rows per prep CTA
#define WO_ROWS 4               // rows per writeout CTA

// scratch: U = [nv1|nv2] k-major, V = [nv2|-nv1] k-major
__device__ float Ug[KTOT * NROW];
__device__ float Vg[KTOT * NROW];
__device__ int   g_unf[NROW];           // 1 = row needs fallback
__device__ float g_kv[NROW * TOPK];     // top-k values per row
__device__ int   g_kj[NROW * TOPK];     // top-k column indices per row
__device__ int   g_cnt[NROW];           // kept count per row

// XLA EmitFastTanh / Eigen generic_fast_tanh_float, with_fma = true:
// clamp +/-7.99881172180175781, fmaf Horner, final mul separate, IEEE div.
__device__ __forceinline__ float xla_tanh(float x) {
    const float kClamp = 7.99881172180175781f;
    float ax = fabsf(x);
    float xc = fminf(fmaxf(x, -kClamp), kClamp);
    float x2 = __fmul_rn(xc, xc);
    float num = -2.76076847742355e-16f;
    num = fmaf(x2, num, 2.00018790482477e-13f);
    num = fmaf(x2, num, -8.60467152213735e-11f);
    num = fmaf(x2, num, 5.12229709037114e-08f);
    num = fmaf(x2, num, 1.48572235717979e-05f);
    num = fmaf(x2, num, 6.37261928875436e-04f);
    num = fmaf(x2, num, 4.89352455891786e-03f);
    num = __fmul_rn(xc, num);
    float den = 1.19825839466702e-06f;
    den = fmaf(x2, den, 1.18534705686654e-04f);
    den = fmaf(x2, den, 2.26843463243900e-03f);
    den = fmaf(x2, den, 4.89352518554385e-03f);
    float r = __fdiv_rn(num, den);
    return (ax < 0.0004f) ? x : r;
}

// ---------------- kernel A: build U, V (k-major), 4x4 register tiling -------
// LDS/fmaf = 0.5 (was 2.0): per d-step each thread loads 4 e + 4 W values and
// does 16 fmaf. 256 threads = 2 layers x 8 row-quads x 16 o-quads.
__global__ void __launch_bounds__(256, 2) prep_kernel(
    const int* __restrict__ idx,
    const float* __restrict__ emb1, const float* __restrict__ emb2,
    const float* __restrict__ W1, const float* __restrict__ b1,
    const float* __restrict__ W2, const float* __restrict__ b2)
{
    __shared__ float W1s[64][65], W2s[64][65];
    __shared__ float e1s[PR_ROWS][65], e2s[PR_ROWS][65];
    __shared__ float nv1s[64][PR_ROWS + 1], nv2s[64][PR_ROWS + 1];
    __shared__ float b1s[64], b2s[64];
    __shared__ int gix[PR_ROWS];

    int tid = threadIdx.x;
    int r0  = blockIdx.x * PR_ROWS;

    if (tid < PR_ROWS) gix[tid] = idx[r0 + tid];
    if (tid < 64) { b1s[tid] = b1[tid]; b2s[tid] = b2[tid]; }
    for (int i = tid; i < 64 * 64; i += 256) {
        int o = i >> 6, d = i & 63;
        W1s[o][d] = W1[i];
        W2s[o][d] = W2[i];
    }
    __syncthreads();          // gix visible
    for (int i = tid; i < PR_ROWS * 64; i += 256) {
        int rb = i >> 6, d = i & 63;
        int g = gix[rb];
        e1s[rb][d] = emb1[(size_t)g * 64 + d];
        e2s[rb][d] = emb2[(size_t)g * 64 + d];
    }
    __syncthreads();

    int layer = tid >> 7;          // 0: layer1, 1: layer2
    int rq    = (tid >> 4) & 7;    // row quad 0..7  (rows rq*4..rq*4+3)
    int oq    = tid & 15;          // o quad 0..15   (o   oq*4..oq*4+3)

    const float (*Ws)[65] = layer ? W2s : W1s;
    const float (*es)[65] = layer ? e2s : e1s;
    const float*  bs      = layer ? b2s : b1s;
    float (*nvs)[PR_ROWS + 1] = layer ? nv2s : nv1s;

    float acc[4][4];
#pragma unroll
    for (int i = 0; i < 4; i++)
#pragma unroll
        for (int j = 0; j < 4; j++) acc[i][j] = 0.f;

#pragma unroll 16
    for (int d = 0; d < 64; d++) {
        float ev[4], wv[4];
#pragma unroll
        for (int i = 0; i < 4; i++) ev[i] = es[rq * 4 + i][d];
#pragma unroll
        for (int j = 0; j < 4; j++) wv[j] = Ws[oq * 4 + j][d];
#pragma unroll
        for (int i = 0; i < 4; i++)
#pragma unroll
            for (int j = 0; j < 4; j++)
                acc[i][j] = fmaf(ev[i], wv[j], acc[i][j]);
    }

#pragma unroll
    for (int i = 0; i < 4; i++)
#pragma unroll
        for (int j = 0; j < 4; j++) {
            int o = oq * 4 + j;
            nvs[o][rq * 4 + i] =
                xla_tanh(__fmul_rn(3.0f, __fadd_rn(acc[i][j], bs[o])));
        }
    __syncthreads();

    // coalesced transposed store-out: 32 consecutive rows per o (128B runs)
    for (int i = tid; i < 64 * PR_ROWS; i += 256) {
        int oo = i >> 5, c = i & 31;
        float n1 = nv1s[oo][c];
        float n2 = nv2s[oo][c];
        size_t base = (size_t)oo * NROW + r0 + c;
        Ug[base]                     = n1;
        Ug[base + (size_t)64 * NROW] = n2;
        Vg[base]                     = n2;
        Vg[base + (size_t)64 * NROW] = -n1;
    }
}

// ---------------- kernel B: stage-1 GEMM (cols 0..255) + ballot top-K -------
#define SM_US 0
#define SM_VS 8192
#define SM_CS 16384
#define SMEM_FLOATS (SM_CS + 64 * 260)
#define SMEM_BYTES (SMEM_FLOATS * 4)

__global__ void __launch_bounds__(NTHR, 1) stage1_kernel()
{
    extern __shared__ float sm[];
    float* Us  = sm + SM_US;
    float* Vs  = sm + SM_VS;
    float* Cs  = sm + SM_CS;

    int tid = threadIdx.x;
    int r0  = blockIdx.x * BM;

    // load resident U tile [128][64]
#pragma unroll
    for (int i = 0; i < 8; i++) {
        int f  = tid + NTHR * i;
        int k  = f >> 4;
        int m4 = (f & 15) << 2;
        *(float4*)&Us[k * 64 + m4] = *(const float4*)&Ug[(size_t)k * NROW + r0 + m4];
    }

    int tx  = tid & 31, ty = tid >> 5;
    int rm0 = ty * 4, rm1 = 32 + ty * 4;
    int cn0 = tx * 4, cn1 = 128 + tx * 4;

    float4 pf0, pf1, pf2, pf3;
    int pk0, pn0, pk1, pn1, pk2, pn2, pk3, pn3;

    {
        int f;
        f = tid;             pk0 = f >> 6; pn0 = (f & 63) << 2;
        f = tid + NTHR;      pk1 = f >> 6; pn1 = (f & 63) << 2;
        f = tid + 2 * NTHR;  pk2 = f >> 6; pn2 = (f & 63) << 2;
        f = tid + 3 * NTHR;  pk3 = f >> 6; pn3 = (f & 63) << 2;
        pf0 = *(const float4*)&Vg[(size_t)pk0 * NROW + pn0];
        pf1 = *(const float4*)&Vg[(size_t)pk1 * NROW + pn1];
        pf2 = *(const float4*)&Vg[(size_t)pk2 * NROW + pn2];
        pf3 = *(const float4*)&Vg[(size_t)pk3 * NROW + pn3];
        *(float4*)&Vs[pk0 * BN + pn0] = pf0;
        *(float4*)&Vs[pk1 * BN + pn1] = pf1;
        *(float4*)&Vs[pk2 * BN + pn2] = pf2;
        *(float4*)&Vs[pk3 * BN + pn3] = pf3;
    }
    __syncthreads();

    float acc[8][8];
#pragma unroll
    for (int i = 0; i < 8; i++)
#pragma unroll
        for (int j = 0; j < 8; j++) acc[i][j] = 0.f;

    int cur = 0;
    for (int kc = 0; kc < NCHUNK; kc++) {
        bool more = (kc + 1 < NCHUNK);
        if (more) {
            size_t base = (size_t)((kc + 1) * KC) * NROW;
            pf0 = *(const float4*)&Vg[base + (size_t)pk0 * NROW + pn0];
            pf1 = *(const float4*)&Vg[base + (size_t)pk1 * NROW + pn1];
            pf2 = *(const float4*)&Vg[base + (size_t)pk2 * NROW + pn2];
            pf3 = *(const float4*)&Vg[base + (size_t)pk3 * NROW + pn3];
        }
        const float* vb = Vs + cur * (KC * BN);
        const float* ub = Us + kc * KC * 64;
#pragma unroll
        for (int k = 0; k < KC; k++) {
            float4 a0 = *(const float4*)&ub[k * 64 + rm0];
            float4 a1 = *(const float4*)&ub[k * 64 + rm1];
            float4 b0 = *(const float4*)&vb[k * BN + cn0];
            float4 b1 = *(const float4*)&vb[k * BN + cn1];
            float av[8] = {a0.x, a0.y, a0.z, a0.w, a1.x, a1.y, a1.z, a1.w};
            float bv[8] = {b0.x, b0.y, b0.z, b0.w, b1.x, b1.y, b1.z, b1.w};
#pragma unroll
            for (int i = 0; i < 8; i++)
#pragma unroll
                for (int j = 0; j < 8; j++)
                    acc[i][j] = fmaf(av[i], bv[j], acc[i][j]);
        }
        if (more) {
            float* vw = Vs + (cur ^ 1) * (KC * BN);
            *(float4*)&vw[pk0 * BN + pn0] = pf0;
            *(float4*)&vw[pk1 * BN + pn1] = pf1;
            *(float4*)&vw[pk2 * BN + pn2] = pf2;
            *(float4*)&vw[pk3 * BN + pn3] = pf3;
        }
        __syncthreads();
        cur ^= 1;
    }

    // stage C tile to smem
#pragma unroll
    for (int i = 0; i < 8; i++) {
        int r = (i < 4) ? (rm0 + i) : (rm1 + i - 4);
        *(float4*)&Cs[r * 260 + cn0] = *(float4*)&acc[i][0];
        *(float4*)&Cs[r * 260 + cn1] = *(float4*)&acc[i][4];
    }
    __syncthreads();

    // ---- warp-parallel ballot epilogue ----
    // Row is "finished" iff >=32 saturated entries (v == vmax) within these
    // 256 cols; then its top-32 = first 32 such columns (ties at vmax break
    // by lowest index; nothing can rank above vmax).
    const float vmax = xla_tanh(30.0f);
    int lane = tid & 31, warp = tid >> 5;
#pragma unroll
    for (int rr = 0; rr < 8; rr++) {
        int row = warp * 8 + rr;
        const float* crow = &Cs[row * 260];
        unsigned masks[8];
        int pcs[8];
#pragma unroll
        for (int c = 0; c < 8; c++) {
            float a = crow[c * 32 + lane];
            bool pred = false;
            if (a > 2.0f) {  // saturation needs a >= ~2.63; guard is safe
                float v = xla_tanh(__fmul_rn(3.0f, a));
                pred = (v >= vmax);
            }
            masks[c] = __ballot_sync(0xffffffffu, pred);
        }
        int total = 0;
#pragma unroll
        for (int c = 0; c < 8; c++) { pcs[c] = total; total += __popc(masks[c]); }
        int grow = r0 + row;
#pragma unroll
        for (int c = 0; c < 8; c++) {
            if ((masks[c] >> lane) & 1u) {
                int rank = pcs[c] + __popc(masks[c] & ((1u << lane) - 1u));
                if (rank < TOPK) {
                    g_kj[(size_t)grow * TOPK + rank] = c * 32 + lane;
                    g_kv[(size_t)grow * TOPK + rank] = vmax;
                }
            }
        }
        if (lane == 0) {
            bool fin = (total >= TOPK);
            g_unf[grow] = fin ? 0 : 1;
            g_cnt[grow] = fin ? TOPK : 0;   // fixed up in writeout if unfinished
        }
    }
}

// ---------------- kernel C: writeout — zero + (rare) exact fallback + scatter
__global__ void __launch_bounds__(256) writeout_kernel(float* __restrict__ out)
{
    __shared__ int   flags[WO_ROWS];
    __shared__ float us[KTOT];
    __shared__ float as[256];
    __shared__ float kv[TOPK];
    __shared__ int   kj[TOPK];
    __shared__ float s_thv, s_thaM;
    __shared__ int   s_cnt, s_done;

    int r0 = blockIdx.x * WO_ROWS;
    int tid = threadIdx.x;

    if (tid < WO_ROWS) flags[tid] = g_unf[r0 + tid];

    // coalesced zero of this block's 4 rows (4 * 8192 floats = 8192 float4)
    float4 z = make_float4(0.f, 0.f, 0.f, 0.f);
    float4* ov = (float4*)(out + (size_t)r0 * NROW);
#pragma unroll
    for (int i = 0; i < WO_ROWS * NROW / 4 / 256; i++)
        ov[tid + 256 * i] = z;

    __syncthreads();   // flags visible; zero ordered before value stores

    // ---- exact full-row fallback for unfinished rows (rare) ----
    const float vmax = xla_tanh(30.0f);
    for (int rr = 0; rr < WO_ROWS; rr++) {
        if (flags[rr] == 0) continue;      // uniform across block
        int row = r0 + rr;

        if (tid < KTOT) us[tid] = Ug[(size_t)tid * NROW + row];
        if (tid == 0) { s_cnt = 0; s_thv = 0.f; s_thaM = 0.f; s_done = 0; }
        __syncthreads();

        for (int jt = 0; jt < NROW / 256; jt++) {
            int j = jt * 256 + tid;
            float acc = 0.f;
#pragma unroll 16
            for (int k = 0; k < KTOT; k++)
                acc = fmaf(us[k], Vg[(size_t)k * NROW + j], acc);
            as[tid] = acc;
            __syncthreads();

            if (tid == 0) {
                int   cnt  = s_cnt;
                float thv  = s_thv;
                float thaM = s_thaM;
                int jbase = jt * 256;
                for (int c = 0; c < 256; c++) {
                    float a = as[c];
                    if (a <= thaM) continue;
                    float v = xla_tanh(__fmul_rn(3.0f, a));
                    int jidx = jbase + c;
                    if (cnt < TOPK) {
                        kv[cnt] = v; kj[cnt] = jidx; cnt++;
                        if (cnt == TOPK) {
                            float mv = kv[0];
                            for (int s = 1; s < TOPK; s++) mv = fminf(mv, kv[s]);
                            thv = mv;
                        }
                    } else if (v > thv) {
                        int ms = 0; float mv = kv[0]; int mj = kj[0];
                        for (int s = 1; s < TOPK; s++) {
                            if (kv[s] < mv || (kv[s] == mv && kj[s] > mj)) { ms = s; mv = kv[s]; mj = kj[s]; }
                        }
                        kv[ms] = v; kj[ms] = jidx;
                        float nm = kv[0];
                        for (int s = 1; s < TOPK; s++) nm = fminf(nm, kv[s]);
                        thv = nm;
                    } else {
                        thaM = fmaxf(thaM, a);
                    }
                }
                s_cnt = cnt; s_thv = thv; s_thaM = thaM;
                if (cnt == TOPK && thv >= vmax) s_done = 1;
            }
            __syncthreads();
            if (s_done) break;
        }

        if (tid == 0) {
            g_cnt[row] = s_cnt;
            for (int s = 0; s < s_cnt; s++) {
                g_kv[(size_t)row * TOPK + s] = kv[s];
                g_kj[(size_t)row * TOPK + s] = kj[s];
            }
        }
        __syncthreads();   // fallback results visible to scatter below
    }

    // ---- scatter values: 128 threads = 4 rows x 32 slots ----
    if (tid < WO_ROWS * TOPK) {
        int row = r0 + (tid >> 5);
        int s   = tid & 31;
        if (s < g_cnt[row]) {
            out[(size_t)row * NROW + g_kj[(size_t)row * TOPK + s]] =
                g_kv[(size_t)row * TOPK + s];
        }
    }
}

extern "C" void kernel_launch(void* const* d_in, const int* in_sizes, int n_in,
                              void* d_out, int out_size)
{
    const int*   idx  = (const int*)d_in[0];
    const float* emb1 = (const float*)d_in[1];
    const float* emb2 = (const float*)d_in[2];
    const float* W1   = (const float*)d_in[3];
    const float* b1   = (const float*)d_in[4];
    const float* W2   = (const float*)d_in[5];
    const float* b2   = (const float*)d_in[6];
    float* out = (float*)d_out;

    static bool configured = false;
    if (!configured) {
        cudaFuncSetAttribute(stage1_kernel, cudaFuncAttributeMaxDynamicSharedMemorySize, SMEM_BYTES);
        configured = true;
    }

    prep_kernel<<<NROW / PR_ROWS, 256>>>(idx, emb1, emb2, W1, b1, W2, b2);
    stage1_kernel<<<NROW / BM, NTHR, SMEM_BYTES>>>();
    writeout_kernel<<<NROW / WO_ROWS, 256>>>(out);
}